// round 11
// baseline (speedup 1.0000x reference)
#include <cuda_runtime.h>
#include <cuda_fp16.h>
#include <cstdint>

// Problem constants
#define BB 32
#define TT 200
#define EE 32
#define HH 128
#define VV 8000
#define MM (BB*TT)   // 6400

// Static scratch: fp16. A (hs) split hi/lo, B (Vw) single fp16.
__device__ alignas(256) __half g_hs_hi[MM * HH];
__device__ alignas(256) __half g_hs_lo[MM * HH];
__device__ alignas(256) __half g_vw[VV * HH];

// ---------------------------------------------------------------------------
// portable PTX helpers (no tcgen05 — compute_103 virtual target)
// ---------------------------------------------------------------------------
__device__ __forceinline__ uint32_t smem_u32(const void* p) {
    uint32_t a;
    asm("{ .reg .u64 t; cvta.to.shared.u64 t, %1; cvt.u32.u64 %0, t; }"
        : "=r"(a) : "l"(p));
    return a;
}
__device__ __forceinline__ void cpasync16(uint32_t dst, const void* src) {
    asm volatile("cp.async.cg.shared.global [%0], [%1], 16;" :: "r"(dst), "l"(src));
}
__device__ __forceinline__ void cpasync_commit() {
    asm volatile("cp.async.commit_group;" ::: "memory");
}
template<int N>
__device__ __forceinline__ void cpasync_wait() {
    asm volatile("cp.async.wait_group %0;" :: "n"(N) : "memory");
}
__device__ __forceinline__ void ldsm4(uint32_t* r, uint32_t addr) {
    asm volatile("ldmatrix.sync.aligned.m8n8.x4.shared.b16 {%0,%1,%2,%3}, [%4];"
                 : "=r"(r[0]), "=r"(r[1]), "=r"(r[2]), "=r"(r[3]) : "r"(addr));
}
__device__ __forceinline__ void ldsm2(uint32_t* r, uint32_t addr) {
    asm volatile("ldmatrix.sync.aligned.m8n8.x2.shared.b16 {%0,%1}, [%2];"
                 : "=r"(r[0]), "=r"(r[1]) : "r"(addr));
}
__device__ __forceinline__ void mma_f16(float* c, const uint32_t* a,
                                        uint32_t b0, uint32_t b1) {
    asm volatile(
        "mma.sync.aligned.m16n8k16.row.col.f32.f16.f16.f32 "
        "{%0,%1,%2,%3}, {%4,%5,%6,%7}, {%8,%9}, {%0,%1,%2,%3};"
        : "+f"(c[0]), "+f"(c[1]), "+f"(c[2]), "+f"(c[3])
        : "r"(a[0]), "r"(a[1]), "r"(a[2]), "r"(a[3]), "r"(b0), "r"(b1));
}
#define FFMA2(acc, a, b) \
    asm("fma.rn.f32x2 %0, %1, %2, %0;" : "+l"(acc) : "l"(a), "l"(b))
#define UNPACK2(lo, hi, v) \
    asm("mov.b64 {%0, %1}, %2;" : "=f"(lo), "=f"(hi) : "l"(v))

__device__ __forceinline__ float ftanh(float x) {
    float e = __expf(2.f * x);
    return 1.f - __fdividef(2.f, e + 1.f);
}

// ---------------------------------------------------------------------------
// Kernel 1: merged prep (round-6 structure, fp16 outputs).
// CTAs 0..31: fused ux + recurrence (one batch each, 256 thr).
// CTAs 32..531: convert Vw -> fp16 (500 CTAs x 1024 float2).
// ---------------------------------------------------------------------------
__global__ __launch_bounds__(256, 1) void prep_kernel(
    const float* __restrict__ x,  const float* __restrict__ Ww,
    const float* __restrict__ Wb, const float* __restrict__ Uw,
    const float* __restrict__ Ub, const float* __restrict__ Vw,
    float* __restrict__ hidden_out) {

    __shared__ alignas(16) float xall[TT * EE];
    __shared__ alignas(16) float hbuf[2][HH];

    if (blockIdx.x >= 32) {
        int base = (blockIdx.x - 32) * 1024 + threadIdx.x;   // float2 index
#pragma unroll
        for (int q = 0; q < 4; q++) {
            int i2 = base + q * 256;
            float2 v = ((const float2*)Vw)[i2];
            ((__half2*)g_vw)[i2] = __floats2half2_rn(v.x, v.y);
        }
        return;
    }

    int b = blockIdx.x;
    int tid = threadIdx.x;
    int wrp = tid >> 5;
    int lane = tid & 31;
    int j = wrp * 16 + (lane & 15);
    int s = lane >> 4;

    // packed weights: 64 floats -> 32 f32x2 (u64)
    unsigned long long w2[32];
    {
        const ulonglong2* wr = (const ulonglong2*)(Ww + j * HH + s * 64);
#pragma unroll
        for (int k = 0; k < 16; k++) {
            ulonglong2 v = wr[k];
            w2[2 * k] = v.x; w2[2 * k + 1] = v.y;
        }
    }
    unsigned long long u2[8];
    {
        const ulonglong2* ur = (const ulonglong2*)(Uw + j * EE + s * 16);
#pragma unroll
        for (int k = 0; k < 4; k++) {
            ulonglong2 v = ur[k];
            u2[2 * k] = v.x; u2[2 * k + 1] = v.y;
        }
    }
    float bj = Ub[j] + Wb[j];

    {
        const float4* xsrc = (const float4*)(x + (size_t)b * TT * EE);
        float4* xdst = (float4*)xall;
        for (int i = tid; i < TT * EE / 4; i += 256) xdst[i] = xsrc[i];
    }
    if (tid < HH) hbuf[0][tid] = 0.f;
    __syncthreads();

    __half* hs_hi = g_hs_hi + (size_t)b * TT * HH;
    __half* hs_lo = g_hs_lo + (size_t)b * TT * HH;

    int cur = 0;
    float hv = 0.f;
    for (int t = 0; t < TT; t++) {
        unsigned long long acc01 = 0ull, acc23 = 0ull;
        const ulonglong2* xt = (const ulonglong2*)(xall + t * EE + s * 16);
#pragma unroll
        for (int e = 0; e < 4; e++) {
            ulonglong2 x2 = xt[e];
            FFMA2(acc01, u2[2 * e], x2.x);
            FFMA2(acc23, u2[2 * e + 1], x2.y);
        }
        const ulonglong2* hb = (const ulonglong2*)(hbuf[cur] + s * 64);
#pragma unroll
        for (int k = 0; k < 16; k++) {
            ulonglong2 h2 = hb[k];
            FFMA2(acc01, w2[2 * k], h2.x);
            FFMA2(acc23, w2[2 * k + 1], h2.y);
        }
        float p0, p1, p2, p3;
        UNPACK2(p0, p1, acc01);
        UNPACK2(p2, p3, acc23);
        float acc = (p0 + p1) + (p2 + p3);
        acc += __shfl_xor_sync(0xffffffffu, acc, 16);
        hv = ftanh(acc + bj);
        __half hi = __float2half_rn(hv);
        if (s == 0) {
            hbuf[cur ^ 1][j] = hv;
            hs_hi[t * HH + j] = hi;
        } else {
            hs_lo[t * HH + j] = __float2half_rn(hv - __half2float(hi));
        }
        __syncthreads();
        cur ^= 1;
    }
    if (s == 0) hidden_out[b * HH + j] = hv;
}

// ---------------------------------------------------------------------------
// Kernel 2: HMMA fp16 2-term GEMM, tile 128x80, 2 CTAs/SM (smem ~84KB).
// C[6400x8000] = hs @ Vw^T + Vb.   D = Ah*B + Al*B  (fp32 accum)
// K=128 resident. 256 thr = 8 warps (4m x 2n), warp tile 32x40.
// SMEM rows: 256B, 16 chunks of 16B, swizzle chunk c -> c ^ (row & 7).
// hs is B-MAJOR here (row m = b*TT + t), exactly as round 6.
// ---------------------------------------------------------------------------
#define SA_HI 0
#define SA_LO 32768
#define SB    65536
#define SBIAS 86016
#define GEMM_SMEM (86016 + 320)

__global__ __launch_bounds__(256, 2) void gemm_hmma_kernel(
    const float* __restrict__ bias, float* __restrict__ C) {
    extern __shared__ char smem[];
    uint32_t sb = smem_u32(smem);
    int tid = threadIdx.x;
    int wid = tid >> 5;
    int lid = tid & 31;
    int warp_m = wid & 3;        // m offset 32*warp_m
    int warp_n = wid >> 2;       // n offset 40*warp_n
    int ntile = blockIdx.x * 80;
    int mtile = blockIdx.y * 128;

    float* bias_s = (float*)(smem + SBIAS);
    if (tid < 80) bias_s[tid] = bias[ntile + tid];

    // B tile (80 rows x 16 chunks, single fp16)
    {
        const uint4* bsrc = (const uint4*)g_vw + (size_t)ntile * 16;
#pragma unroll
        for (int i = tid; i < 1280; i += 256) {
            int row = i >> 4, c = i & 15;
            uint32_t off = (uint32_t)row * 256u + (uint32_t)((c ^ (row & 7)) << 4);
            cpasync16(sb + SB + off, bsrc + i);
        }
    }
    // A tiles (128 rows x 16 chunks, hi+lo)
    {
        const uint4* aH = (const uint4*)g_hs_hi + (size_t)mtile * 16;
        const uint4* aL = (const uint4*)g_hs_lo + (size_t)mtile * 16;
#pragma unroll
        for (int i = tid; i < 2048; i += 256) {
            int row = i >> 4, c = i & 15;
            uint32_t off = (uint32_t)row * 256u + (uint32_t)((c ^ (row & 7)) << 4);
            cpasync16(sb + SA_HI + off, aH + i);
            cpasync16(sb + SA_LO + off, aL + i);
        }
    }
    cpasync_commit();
    cpasync_wait<0>();
    __syncthreads();

    // lane geometry
    int ra = warp_m * 32 + (lid & 15);
    int r7 = ra & 7;
    uint32_t aH_row = sb + SA_HI + (uint32_t)ra * 256u;
    uint32_t aL_row = sb + SA_LO + (uint32_t)ra * 256u;
    int ca = (lid >> 4);

    int nb4 = warp_n * 40 + (lid & 7) + ((lid >> 4) << 3);
    int nb2 = warp_n * 40 + 32 + (lid & 7);
    int n7 = lid & 7;
    int cb = (lid >> 3) & 1;
    uint32_t b4 = sb + SB + (uint32_t)nb4 * 256u;
    uint32_t b2 = sb + SB + (uint32_t)nb2 * 256u;

    float acc[2][5][4];
#pragma unroll
    for (int im = 0; im < 2; im++)
#pragma unroll
        for (int s = 0; s < 5; s++)
#pragma unroll
            for (int q = 0; q < 4; q++) acc[im][s][q] = 0.f;

#pragma unroll
    for (int k = 0; k < 8; k++) {
        uint32_t offA = (uint32_t)(((k * 2 + ca) ^ r7) << 4);
        uint32_t offB = (uint32_t)(((k * 2 + cb) ^ n7) << 4);
        uint32_t aH[8], aL[8], bf[10];
        ldsm4(aH,     aH_row + offA);
        ldsm4(aH + 4, aH_row + 4096 + offA);
        ldsm4(aL,     aL_row + offA);
        ldsm4(aL + 4, aL_row + 4096 + offA);
        ldsm4(bf,     b4 + offB);
        ldsm4(bf + 4, b4 + 4096 + offB);
        ldsm2(bf + 8, b2 + offB);
#pragma unroll
        for (int im = 0; im < 2; im++)
#pragma unroll
            for (int s = 0; s < 5; s++)
                mma_f16(acc[im][s], aH + im * 4, bf[s * 2], bf[s * 2 + 1]);
#pragma unroll
        for (int im = 0; im < 2; im++)
#pragma unroll
            for (int s = 0; s < 5; s++)
                mma_f16(acc[im][s], aL + im * 4, bf[s * 2], bf[s * 2 + 1]);
    }

    // epilogue (b-major hs rows -> C rows directly, as round 6)
    int r0 = mtile + warp_m * 32 + (lid >> 2);
    int cbase = warp_n * 40 + (lid & 3) * 2;
#pragma unroll
    for (int im = 0; im < 2; im++) {
#pragma unroll
        for (int s = 0; s < 5; s++) {
            int col = cbase + s * 8;
            float b0 = bias_s[col], b1 = bias_s[col + 1];
            float* p0 = C + (size_t)(r0 + im * 16) * VV + ntile + col;
            float* p1 = p0 + (size_t)8 * VV;
            *(float2*)p0 = make_float2(acc[im][s][0] + b0, acc[im][s][1] + b1);
            *(float2*)p1 = make_float2(acc[im][s][2] + b0, acc[im][s][3] + b1);
        }
    }
}

// ---------------------------------------------------------------------------
extern "C" void kernel_launch(void* const* d_in, const int* in_sizes, int n_in,
                              void* d_out, int out_size) {
    const float* x  = (const float*)d_in[0];
    const float* Ww = (const float*)d_in[1];
    const float* Wb = (const float*)d_in[2];
    const float* Uw = (const float*)d_in[3];
    const float* Ub = (const float*)d_in[4];
    const float* Vw = (const float*)d_in[5];
    const float* Vb = (const float*)d_in[6];

    float* out    = (float*)d_out;
    float* hidden = out + (size_t)BB * TT * VV;

    cudaFuncSetAttribute(gemm_hmma_kernel,
                         cudaFuncAttributeMaxDynamicSharedMemorySize, GEMM_SMEM);

    prep_kernel<<<532, 256>>>(x, Ww, Wb, Uw, Ub, Vw, hidden);
    dim3 grid(VV / 80, MM / 128);
    gemm_hmma_kernel<<<grid, 256, GEMM_SMEM>>>(Vb, out);
}

// round 14
// speedup vs baseline: 1.1857x; 1.1857x over previous
#include <cuda_runtime.h>
#include <cuda_fp16.h>
#include <cstdint>

// Problem constants
#define BB 32
#define TT 200
#define EE 32
#define HH 128
#define VV 8000
#define MM (BB*TT)   // 6400

// Static scratch: plain fp16 copies. hs is B-MAJOR (row m = b*TT + t).
__device__ alignas(256) __half g_hs[MM * HH];
__device__ alignas(256) __half g_vw[VV * HH];

// ---------------------------------------------------------------------------
// portable PTX helpers (no tcgen05 — compute_103 virtual target)
// ---------------------------------------------------------------------------
__device__ __forceinline__ uint32_t smem_u32(const void* p) {
    uint32_t a;
    asm("{ .reg .u64 t; cvta.to.shared.u64 t, %1; cvt.u32.u64 %0, t; }"
        : "=r"(a) : "l"(p));
    return a;
}
__device__ __forceinline__ void cpasync16(uint32_t dst, const void* src) {
    asm volatile("cp.async.cg.shared.global [%0], [%1], 16;" :: "r"(dst), "l"(src));
}
__device__ __forceinline__ void cpasync_commit() {
    asm volatile("cp.async.commit_group;" ::: "memory");
}
template<int N>
__device__ __forceinline__ void cpasync_wait() {
    asm volatile("cp.async.wait_group %0;" :: "n"(N) : "memory");
}
__device__ __forceinline__ void ldsm4(uint32_t* r, uint32_t addr) {
    asm volatile("ldmatrix.sync.aligned.m8n8.x4.shared.b16 {%0,%1,%2,%3}, [%4];"
                 : "=r"(r[0]), "=r"(r[1]), "=r"(r[2]), "=r"(r[3]) : "r"(addr));
}
__device__ __forceinline__ void ldsm2(uint32_t* r, uint32_t addr) {
    asm volatile("ldmatrix.sync.aligned.m8n8.x2.shared.b16 {%0,%1}, [%2];"
                 : "=r"(r[0]), "=r"(r[1]) : "r"(addr));
}
__device__ __forceinline__ void mma_f16(float* c, const uint32_t* a,
                                        uint32_t b0, uint32_t b1) {
    asm volatile(
        "mma.sync.aligned.m16n8k16.row.col.f32.f16.f16.f32 "
        "{%0,%1,%2,%3}, {%4,%5,%6,%7}, {%8,%9}, {%0,%1,%2,%3};"
        : "+f"(c[0]), "+f"(c[1]), "+f"(c[2]), "+f"(c[3])
        : "r"(a[0]), "r"(a[1]), "r"(a[2]), "r"(a[3]), "r"(b0), "r"(b1));
}
#define FFMA2(acc, a, b) \
    asm("fma.rn.f32x2 %0, %1, %2, %0;" : "+l"(acc) : "l"(a), "l"(b))
#define UNPACK2(lo, hi, v) \
    asm("mov.b64 {%0, %1}, %2;" : "=f"(lo), "=f"(hi) : "l"(v))

__device__ __forceinline__ float ftanh(float x) {
    float e = __expf(2.f * x);
    return 1.f - __fdividef(2.f, e + 1.f);
}

// ---------------------------------------------------------------------------
// Kernel 1: merged prep.
// CTAs 0..31: fused ux + recurrence (one batch each, 256 thr).
// CTAs 32..531: convert Vw -> fp16 (500 CTAs x 1024 float2).
// ---------------------------------------------------------------------------
__global__ __launch_bounds__(256, 1) void prep_kernel(
    const float* __restrict__ x,  const float* __restrict__ Ww,
    const float* __restrict__ Wb, const float* __restrict__ Uw,
    const float* __restrict__ Ub, const float* __restrict__ Vw,
    float* __restrict__ hidden_out) {

    __shared__ alignas(16) float xall[TT * EE];
    __shared__ alignas(16) float hbuf[2][HH];

    if (blockIdx.x >= 32) {
        int base = (blockIdx.x - 32) * 1024 + threadIdx.x;   // float2 index
#pragma unroll
        for (int q = 0; q < 4; q++) {
            int i2 = base + q * 256;
            float2 v = ((const float2*)Vw)[i2];
            ((__half2*)g_vw)[i2] = __floats2half2_rn(v.x, v.y);
        }
        return;
    }

    int b = blockIdx.x;
    int tid = threadIdx.x;
    int wrp = tid >> 5;
    int lane = tid & 31;
    int j = wrp * 16 + (lane & 15);
    int s = lane >> 4;

    // packed weights: 64 floats -> 32 f32x2 (u64)
    unsigned long long w2[32];
    {
        const ulonglong2* wr = (const ulonglong2*)(Ww + j * HH + s * 64);
#pragma unroll
        for (int k = 0; k < 16; k++) {
            ulonglong2 v = wr[k];
            w2[2 * k] = v.x; w2[2 * k + 1] = v.y;
        }
    }
    unsigned long long u2[8];
    {
        const ulonglong2* ur = (const ulonglong2*)(Uw + j * EE + s * 16);
#pragma unroll
        for (int k = 0; k < 4; k++) {
            ulonglong2 v = ur[k];
            u2[2 * k] = v.x; u2[2 * k + 1] = v.y;
        }
    }
    float bj = Ub[j] + Wb[j];

    {
        const float4* xsrc = (const float4*)(x + (size_t)b * TT * EE);
        float4* xdst = (float4*)xall;
        for (int i = tid; i < TT * EE / 4; i += 256) xdst[i] = xsrc[i];
    }
    if (tid < HH) hbuf[0][tid] = 0.f;
    __syncthreads();

    __half* hs = g_hs + (size_t)b * TT * HH;

    int cur = 0;
    float hv = 0.f;
    for (int t = 0; t < TT; t++) {
        unsigned long long acc01 = 0ull, acc23 = 0ull;
        const ulonglong2* xt = (const ulonglong2*)(xall + t * EE + s * 16);
#pragma unroll
        for (int e = 0; e < 4; e++) {
            ulonglong2 x2 = xt[e];
            FFMA2(acc01, u2[2 * e], x2.x);
            FFMA2(acc23, u2[2 * e + 1], x2.y);
        }
        const ulonglong2* hb = (const ulonglong2*)(hbuf[cur] + s * 64);
#pragma unroll
        for (int k = 0; k < 16; k++) {
            ulonglong2 h2 = hb[k];
            FFMA2(acc01, w2[2 * k], h2.x);
            FFMA2(acc23, w2[2 * k + 1], h2.y);
        }
        float p0, p1, p2, p3;
        UNPACK2(p0, p1, acc01);
        UNPACK2(p2, p3, acc23);
        float acc = (p0 + p1) + (p2 + p3);
        acc += __shfl_xor_sync(0xffffffffu, acc, 16);
        hv = ftanh(acc + bj);
        if (s == 0) {
            hbuf[cur ^ 1][j] = hv;
            hs[t * HH + j] = __float2half_rn(hv);
        }
        __syncthreads();
        cur ^= 1;
    }
    if (s == 0) hidden_out[b * HH + j] = hv;
}

// ---------------------------------------------------------------------------
// Kernel 2: plain fp16 HMMA GEMM, tile 128x80, 3 CTAs/SM (smem ~52.5KB).
// C[6400x8000] = hs @ Vw^T + Vb  (fp32 accum).
// K=128 resident. 256 thr = 8 warps (4m x 2n), warp tile 32x40.
// SMEM rows: 256B, 16 chunks of 16B, swizzle chunk c -> c ^ (row & 7).
// ---------------------------------------------------------------------------
#define SA    0
#define SB    32768
#define SBIAS 53248
#define GEMM_SMEM (53248 + 320)

__global__ __launch_bounds__(256, 3) void gemm_hmma_kernel(
    const float* __restrict__ bias, float* __restrict__ C) {
    extern __shared__ char smem[];
    uint32_t sb = smem_u32(smem);
    int tid = threadIdx.x;
    int wid = tid >> 5;
    int lid = tid & 31;
    int warp_m = wid & 3;        // m offset 32*warp_m
    int warp_n = wid >> 2;       // n offset 40*warp_n
    int ntile = blockIdx.x * 80;
    int mtile = blockIdx.y * 128;

    float* bias_s = (float*)(smem + SBIAS);
    if (tid < 80) bias_s[tid] = bias[ntile + tid];

    // B tile (80 rows x 16 chunks)
    {
        const uint4* bsrc = (const uint4*)g_vw + (size_t)ntile * 16;
#pragma unroll
        for (int i = tid; i < 1280; i += 256) {
            int row = i >> 4, c = i & 15;
            uint32_t off = (uint32_t)row * 256u + (uint32_t)((c ^ (row & 7)) << 4);
            cpasync16(sb + SB + off, bsrc + i);
        }
    }
    // A tile (128 rows x 16 chunks)
    {
        const uint4* asrc = (const uint4*)g_hs + (size_t)mtile * 16;
#pragma unroll
        for (int i = tid; i < 2048; i += 256) {
            int row = i >> 4, c = i & 15;
            uint32_t off = (uint32_t)row * 256u + (uint32_t)((c ^ (row & 7)) << 4);
            cpasync16(sb + SA + off, asrc + i);
        }
    }
    cpasync_commit();
    cpasync_wait<0>();
    __syncthreads();

    // lane geometry
    int ra = warp_m * 32 + (lid & 15);
    int r7 = ra & 7;
    uint32_t a_row = sb + SA + (uint32_t)ra * 256u;
    int ca = (lid >> 4);

    int nb4 = warp_n * 40 + (lid & 7) + ((lid >> 4) << 3);
    int nb2 = warp_n * 40 + 32 + (lid & 7);
    int n7 = lid & 7;
    int cb = (lid >> 3) & 1;
    uint32_t b4 = sb + SB + (uint32_t)nb4 * 256u;
    uint32_t b2 = sb + SB + (uint32_t)nb2 * 256u;

    float acc[2][5][4];
#pragma unroll
    for (int im = 0; im < 2; im++)
#pragma unroll
        for (int s = 0; s < 5; s++)
#pragma unroll
            for (int q = 0; q < 4; q++) acc[im][s][q] = 0.f;

#pragma unroll
    for (int k = 0; k < 8; k++) {
        uint32_t offA = (uint32_t)(((k * 2 + ca) ^ r7) << 4);
        uint32_t offB = (uint32_t)(((k * 2 + cb) ^ n7) << 4);
        uint32_t af[8], bf[10];
        ldsm4(af,     a_row + offA);
        ldsm4(af + 4, a_row + 4096 + offA);
        ldsm4(bf,     b4 + offB);
        ldsm4(bf + 4, b4 + 4096 + offB);
        ldsm2(bf + 8, b2 + offB);
#pragma unroll
        for (int im = 0; im < 2; im++)
#pragma unroll
            for (int s = 0; s < 5; s++)
                mma_f16(acc[im][s], af + im * 4, bf[s * 2], bf[s * 2 + 1]);
    }

    // epilogue (b-major hs rows -> C rows directly)
    int r0 = mtile + warp_m * 32 + (lid >> 2);
    int cbase = warp_n * 40 + (lid & 3) * 2;
#pragma unroll
    for (int im = 0; im < 2; im++) {
#pragma unroll
        for (int s = 0; s < 5; s++) {
            int col = cbase + s * 8;
            float b0 = bias_s[col], b1 = bias_s[col + 1];
            float* p0 = C + (size_t)(r0 + im * 16) * VV + ntile + col;
            float* p1 = p0 + (size_t)8 * VV;
            *(float2*)p0 = make_float2(acc[im][s][0] + b0, acc[im][s][1] + b1);
            *(float2*)p1 = make_float2(acc[im][s][2] + b0, acc[im][s][3] + b1);
        }
    }
}

// ---------------------------------------------------------------------------
extern "C" void kernel_launch(void* const* d_in, const int* in_sizes, int n_in,
                              void* d_out, int out_size) {
    const float* x  = (const float*)d_in[0];
    const float* Ww = (const float*)d_in[1];
    const float* Wb = (const float*)d_in[2];
    const float* Uw = (const float*)d_in[3];
    const float* Ub = (const float*)d_in[4];
    const float* Vw = (const float*)d_in[5];
    const float* Vb = (const float*)d_in[6];

    float* out    = (float*)d_out;
    float* hidden = out + (size_t)BB * TT * VV;

    cudaFuncSetAttribute(gemm_hmma_kernel,
                         cudaFuncAttributeMaxDynamicSharedMemorySize, GEMM_SMEM);

    prep_kernel<<<532, 256>>>(x, Ww, Wb, Uw, Ub, Vw, hidden);
    dim3 grid(VV / 80, MM / 128);
    gemm_hmma_kernel<<<grid, 256, GEMM_SMEM>>>(Vb, out);
}

// round 15
// speedup vs baseline: 1.2057x; 1.0169x over previous
#include <cuda_runtime.h>
#include <cuda_fp16.h>
#include <cstdint>

// Problem constants
#define BB 32
#define TT 200
#define EE 32
#define HH 128
#define VV 8000
#define MM (BB*TT)   // 6400

#define N_MTILES 50          // t-major: tile mt = timesteps [4mt,4mt+4) x 32 batches
#define N_NTILES 50          // 8000 / 160
#define N_JOBS   (N_MTILES * N_NTILES)
#define GRID_FUSED 304       // 2 CTAs x 152 SMs (GB300)
#define N_CONSUMERS 240      // 304 - 32 producers - 32 exited partners
#define VW_CHUNK4 1067       // float4s per consumer chunk (240*1067 >= 256000)

// Static scratch. hs is T-MAJOR: row m = t*32 + b. Plain fp16.
__device__ alignas(256) __half g_hs[MM * HH];
__device__ alignas(256) __half g_vw[VV * HH];
__device__ unsigned g_cnt[N_MTILES];   // producers done per 4-step chunk
__device__ unsigned g_ticket;          // consumer job ticket
__device__ unsigned g_vwdone;          // consumers done with vw convert

// ---------------------------------------------------------------------------
// portable PTX helpers
// ---------------------------------------------------------------------------
__device__ __forceinline__ uint32_t smem_u32(const void* p) {
    uint32_t a;
    asm("{ .reg .u64 t; cvta.to.shared.u64 t, %1; cvt.u32.u64 %0, t; }"
        : "=r"(a) : "l"(p));
    return a;
}
__device__ __forceinline__ void cpasync16(uint32_t dst, const void* src) {
    asm volatile("cp.async.cg.shared.global [%0], [%1], 16;" :: "r"(dst), "l"(src));
}
__device__ __forceinline__ void cpasync_commit() {
    asm volatile("cp.async.commit_group;" ::: "memory");
}
template<int N>
__device__ __forceinline__ void cpasync_wait() {
    asm volatile("cp.async.wait_group %0;" :: "n"(N) : "memory");
}
__device__ __forceinline__ void ldsm4(uint32_t* r, uint32_t addr) {
    asm volatile("ldmatrix.sync.aligned.m8n8.x4.shared.b16 {%0,%1,%2,%3}, [%4];"
                 : "=r"(r[0]), "=r"(r[1]), "=r"(r[2]), "=r"(r[3]) : "r"(addr));
}
__device__ __forceinline__ void mma_f16(float* c, const uint32_t* a,
                                        uint32_t b0, uint32_t b1) {
    asm volatile(
        "mma.sync.aligned.m16n8k16.row.col.f32.f16.f16.f32 "
        "{%0,%1,%2,%3}, {%4,%5,%6,%7}, {%8,%9}, {%0,%1,%2,%3};"
        : "+f"(c[0]), "+f"(c[1]), "+f"(c[2]), "+f"(c[3])
        : "r"(a[0]), "r"(a[1]), "r"(a[2]), "r"(a[3]), "r"(b0), "r"(b1));
}
#define FFMA2(acc, a, b) \
    asm("fma.rn.f32x2 %0, %1, %2, %0;" : "+l"(acc) : "l"(a), "l"(b))
#define UNPACK2(lo, hi, v) \
    asm("mov.b64 {%0, %1}, %2;" : "=f"(lo), "=f"(hi) : "l"(v))

__device__ __forceinline__ float ftanh(float x) {
    float e = __expf(2.f * x);
    return 1.f - __fdividef(2.f, e + 1.f);
}
__device__ __forceinline__ void red_release(unsigned* p) {
    asm volatile("red.release.gpu.global.add.u32 [%0], 1;" :: "l"(p) : "memory");
}
__device__ __forceinline__ unsigned load_acquire(const unsigned* p) {
    unsigned v;
    asm volatile("ld.acquire.gpu.global.u32 %0, [%1];" : "=r"(v) : "l"(p) : "memory");
    return v;
}

// ---------------------------------------------------------------------------
// Kernel 1: zero flags/ticket (graph replays re-zero every launch).
// ---------------------------------------------------------------------------
__global__ void zero_kernel() {
    int t = threadIdx.x;   // 64 threads
    if (t < N_MTILES) g_cnt[t] = 0;
    else if (t == N_MTILES)     g_ticket = 0;
    else if (t == N_MTILES + 1) g_vwdone = 0;
}

// ---------------------------------------------------------------------------
// GEMM tile: 128x160, K=128 resident, plain fp16 HMMA, fp32 accum.
// 8 warps (4m x 2n), warp tile 32x80. SMEM rows 256B, swizzle c ^= (row&7).
// ---------------------------------------------------------------------------
#define SA    0
#define SB    32768
#define SBIAS 73728
#define GEMM_SMEM (73728 + 640)

__device__ __forceinline__ void gemm_tile(char* smem, uint32_t sb,
                                          int mtile, int ntile,
                                          const float* __restrict__ bias,
                                          float* __restrict__ C, int tid) {
    int wid = tid >> 5;
    int lid = tid & 31;
    int warp_m = wid & 3;        // 32 rows each
    int warp_n = wid >> 2;       // 80 cols each

    float* bias_s = (float*)(smem + SBIAS);
    if (tid < 160) bias_s[tid] = bias[ntile + tid];

    // B tile (160 rows x 16 chunks)
    {
        const uint4* bsrc = (const uint4*)g_vw + (size_t)ntile * 16;
#pragma unroll
        for (int i = tid; i < 2560; i += 256) {
            int row = i >> 4, c = i & 15;
            uint32_t off = (uint32_t)row * 256u + (uint32_t)((c ^ (row & 7)) << 4);
            cpasync16(sb + SB + off, bsrc + i);
        }
    }
    // A tile (128 rows x 16 chunks)
    {
        const uint4* asrc = (const uint4*)g_hs + (size_t)mtile * 16;
#pragma unroll
        for (int i = tid; i < 2048; i += 256) {
            int row = i >> 4, c = i & 15;
            uint32_t off = (uint32_t)row * 256u + (uint32_t)((c ^ (row & 7)) << 4);
            cpasync16(sb + SA + off, asrc + i);
        }
    }
    cpasync_commit();
    cpasync_wait<0>();
    __syncthreads();

    // lane geometry
    int ra = warp_m * 32 + (lid & 15);
    int r7 = ra & 7;
    uint32_t a_row = sb + SA + (uint32_t)ra * 256u;
    int ca = (lid >> 4);

    int nb = warp_n * 80 + (lid & 7) + ((lid >> 4) << 3);
    int n7 = lid & 7;
    int cb = (lid >> 3) & 1;
    uint32_t b_row = sb + SB + (uint32_t)nb * 256u;

    float acc[2][10][4];
#pragma unroll
    for (int im = 0; im < 2; im++)
#pragma unroll
        for (int s = 0; s < 10; s++)
#pragma unroll
            for (int q = 0; q < 4; q++) acc[im][s][q] = 0.f;

#pragma unroll
    for (int k = 0; k < 8; k++) {
        uint32_t offA = (uint32_t)(((k * 2 + ca) ^ r7) << 4);
        uint32_t offB = (uint32_t)(((k * 2 + cb) ^ n7) << 4);
        uint32_t af[8], bf[20];
        ldsm4(af,     a_row + offA);
        ldsm4(af + 4, a_row + 4096 + offA);
#pragma unroll
        for (int jj = 0; jj < 5; jj++)
            ldsm4(bf + jj * 4, b_row + jj * 4096 + offB);
#pragma unroll
        for (int im = 0; im < 2; im++)
#pragma unroll
            for (int s = 0; s < 10; s++) {
                int bi = (s >> 1) * 4 + (s & 1) * 2;
                mma_f16(acc[im][s], af + im * 4, bf[bi], bf[bi + 1]);
            }
    }

    // epilogue. hs row r = t*32 + b  ->  C row index b*TT + t
    int r0 = mtile + warp_m * 32 + (lid >> 2);
    int cbase = warp_n * 80 + (lid & 3) * 2;
#pragma unroll
    for (int im = 0; im < 2; im++) {
        int rA = r0 + im * 16;
        int rB = rA + 8;
        float* cA = C + ((size_t)((rA & 31) * TT + (rA >> 5))) * VV + ntile;
        float* cB = C + ((size_t)((rB & 31) * TT + (rB >> 5))) * VV + ntile;
#pragma unroll
        for (int s = 0; s < 10; s++) {
            int col = cbase + s * 8;
            float b0 = bias_s[col], b1 = bias_s[col + 1];
            *(float2*)(cA + col) = make_float2(acc[im][s][0] + b0, acc[im][s][1] + b1);
            *(float2*)(cB + col) = make_float2(acc[im][s][2] + b0, acc[im][s][3] + b1);
        }
    }
}

// ---------------------------------------------------------------------------
// Kernel 2 (fused persistent), grid 304:
//   bids 0..31    : producers (recurrence for batch = bid), then join pool.
//   bids 152..183 : EXIT — wave-2 partners of producer SMs under
//                   LUT[bid % 152] (GB300 has 152 SMs).
//   others (240)  : consumers — Vw->fp16 convert first, then GEMM jobs
//                   gated on per-4-step chunk counters.
// ---------------------------------------------------------------------------
__global__ __launch_bounds__(256, 2) void fused_kernel(
    const float* __restrict__ x,  const float* __restrict__ Ww,
    const float* __restrict__ Wb, const float* __restrict__ Uw,
    const float* __restrict__ Ub, const float* __restrict__ Vw,
    const float* __restrict__ Vb,
    float* __restrict__ out, float* __restrict__ hidden_out) {

    extern __shared__ char smem[];
    uint32_t sb = smem_u32(smem);
    __shared__ unsigned s_job;
    int tid = threadIdx.x;
    int bid = blockIdx.x;

    if (bid >= 152 && bid < 184) return;   // isolate producer SMs

    if (bid < 32) {
        // ================= producer: recurrence for batch b =================
        int b = bid;
        int wrp = tid >> 5;
        int lane = tid & 31;
        int j = wrp * 16 + (lane & 15);
        int s = lane >> 4;

        float* xall = (float*)smem;                    // TT*EE floats = 25.6KB
        float* hbuf = (float*)(smem + TT * EE * 4);    // 2*HH floats

        unsigned long long w2[32];
        {
            const ulonglong2* wr = (const ulonglong2*)(Ww + j * HH + s * 64);
#pragma unroll
            for (int k = 0; k < 16; k++) {
                ulonglong2 v = wr[k];
                w2[2 * k] = v.x; w2[2 * k + 1] = v.y;
            }
        }
        unsigned long long u2[8];
        {
            const ulonglong2* ur = (const ulonglong2*)(Uw + j * EE + s * 16);
#pragma unroll
            for (int k = 0; k < 4; k++) {
                ulonglong2 v = ur[k];
                u2[2 * k] = v.x; u2[2 * k + 1] = v.y;
            }
        }
        float bj = Ub[j] + Wb[j];

        {
            const float4* xsrc = (const float4*)(x + (size_t)b * TT * EE);
            float4* xdst = (float4*)xall;
            for (int i = tid; i < TT * EE / 4; i += 256) xdst[i] = xsrc[i];
        }
        if (tid < HH) hbuf[tid] = 0.f;
        __syncthreads();

        int cur = 0;
        float hv = 0.f;
        for (int t = 0; t < TT; t++) {
            unsigned long long acc01 = 0ull, acc23 = 0ull;
            const ulonglong2* xt = (const ulonglong2*)(xall + t * EE + s * 16);
#pragma unroll
            for (int e = 0; e < 4; e++) {
                ulonglong2 x2 = xt[e];
                FFMA2(acc01, u2[2 * e], x2.x);
                FFMA2(acc23, u2[2 * e + 1], x2.y);
            }
            const ulonglong2* hb = (const ulonglong2*)(hbuf + cur * HH + s * 64);
#pragma unroll
            for (int k = 0; k < 16; k++) {
                ulonglong2 h2 = hb[k];
                FFMA2(acc01, w2[2 * k], h2.x);
                FFMA2(acc23, w2[2 * k + 1], h2.y);
            }
            float p0, p1, p2, p3;
            UNPACK2(p0, p1, acc01);
            UNPACK2(p2, p3, acc23);
            float acc = (p0 + p1) + (p2 + p3);
            acc += __shfl_xor_sync(0xffffffffu, acc, 16);
            hv = ftanh(acc + bj);
            if (s == 0) {
                hbuf[(cur ^ 1) * HH + j] = hv;
                g_hs[(size_t)(t * BB + b) * HH + j] = __float2half_rn(hv);  // T-MAJOR
            }
            __syncthreads();
            if (((t & 3) == 3) && tid == 0) red_release(g_cnt + (t >> 2));
            cur ^= 1;
        }
        if (s == 0) hidden_out[b * HH + j] = hv;
        // fall through to consumer pool
    } else {
        // ============ consumer pre-work: Vw -> fp16 (static chunks) =========
        int cidx = (bid < 152) ? (bid - 32) : (bid - 184 + 120);   // 0..239
        int base4 = cidx * VW_CHUNK4;
#pragma unroll
        for (int q = 0; q < 5; q++) {
            int i4 = base4 + q * 256 + tid;
            if (i4 < base4 + VW_CHUNK4 && i4 < VV * HH / 4) {
                float4 v = ((const float4*)Vw)[i4];
                ((__half2*)g_vw)[i4 * 2]     = __floats2half2_rn(v.x, v.y);
                ((__half2*)g_vw)[i4 * 2 + 1] = __floats2half2_rn(v.z, v.w);
            }
        }
        __syncthreads();
        if (tid == 0) red_release(&g_vwdone);
    }

    // gate: full Vw convert must be visible before any tile load
    if (tid == 0) {
        while (load_acquire(&g_vwdone) < (unsigned)N_CONSUMERS) __nanosleep(128);
    }
    __syncthreads();

    // ======================= consumer: GEMM jobs ===========================
    for (;;) {
        if (tid == 0) s_job = atomicAdd(&g_ticket, 1u);
        __syncthreads();          // broadcast job + guard smem reuse
        unsigned j = s_job;
        if (j >= N_JOBS) break;
        int mt = (int)(j / N_NTILES);
        int ntile = (int)(j % N_NTILES) * 160;
        if (tid == 0) {
            while (load_acquire(g_cnt + mt) < 32u) __nanosleep(64);
        }
        __syncthreads();
        gemm_tile(smem, sb, mt * 128, ntile, Vb, out, tid);
    }
}

// ---------------------------------------------------------------------------
extern "C" void kernel_launch(void* const* d_in, const int* in_sizes, int n_in,
                              void* d_out, int out_size) {
    const float* x  = (const float*)d_in[0];
    const float* Ww = (const float*)d_in[1];
    const float* Wb = (const float*)d_in[2];
    const float* Uw = (const float*)d_in[3];
    const float* Ub = (const float*)d_in[4];
    const float* Vw = (const float*)d_in[5];
    const float* Vb = (const float*)d_in[6];

    float* out    = (float*)d_out;
    float* hidden = out + (size_t)BB * TT * VV;

    cudaFuncSetAttribute(fused_kernel,
                         cudaFuncAttributeMaxDynamicSharedMemorySize, GEMM_SMEM);

    zero_kernel<<<1, 64>>>();
    fused_kernel<<<GRID_FUSED, 256, GEMM_SMEM>>>(x, Ww, Wb, Uw, Ub, Vw, Vb,
                                                 out, hidden);
}